// round 2
// baseline (speedup 1.0000x reference)
#include <cuda_runtime.h>

#define CCLS 19
#define NIMG 4
#define HDIM 768
#define HW (HDIM*HDIM)        /* 589824 */
#define TOT (NIMG*HW)         /* 2359296 */
#define NC (NIMG*CCLS)        /* 76 */

#define NBLK 592
#define NTHR 256

// Global accumulators (zeroed by zero_kernel each launch -> deterministic, graph-safe)
__device__ double g_segsum[NC];
__device__ double g_attsum[NC];
__device__ unsigned int g_scnt[NC];
__device__ unsigned int g_acnt[NC];
__device__ double g_bpos;
__device__ double g_bneg;
__device__ unsigned long long g_posn;

__global__ void zero_kernel() {
    int i = threadIdx.x;
    if (i < NC) { g_segsum[i] = 0.0; g_attsum[i] = 0.0; g_scnt[i] = 0u; g_acnt[i] = 0u; }
    if (i == 0) { g_bpos = 0.0; g_bneg = 0.0; g_posn = 0ull; }
}

__global__ __launch_bounds__(NTHR, 4) void main_kernel(
    const float* __restrict__ segin, const float* __restrict__ edgein,
    const int* __restrict__ segmask, const int* __restrict__ edgemask)
{
    __shared__ float sh_seg[NC];
    __shared__ float sh_att[NC];
    __shared__ unsigned int sh_sc[NC];
    __shared__ unsigned int sh_ac[NC];
    __shared__ float swp[NTHR / 32];
    __shared__ float swn[NTHR / 32];
    __shared__ unsigned int swc[NTHR / 32];

    const int t = threadIdx.x;
    for (int i = t; i < NC; i += NTHR) {
        sh_seg[i] = 0.f; sh_att[i] = 0.f; sh_sc[i] = 0u; sh_ac[i] = 0u;
    }
    __syncthreads();

    float bp = 0.f, bn = 0.f;
    unsigned int pc = 0;

    const int stride = NBLK * NTHR;
    for (int pix = blockIdx.x * NTHR + t; pix < TOT; pix += stride) {
        const int n = pix / HW;               // constant divisor -> mul/shift
        const int p = pix - n * HW;
        const float* base = segin + (size_t)n * (CCLS * HW) + p;
        const int tc = segmask[pix];          // guaranteed in [0, 19)

        // Load 19 channel logits (coalesced per warp per channel), track max and
        // the target-class value via unrolled selects (no dynamic reg indexing).
        float x[CCLS];
        float m = -1e30f, xt = 0.f;
        #pragma unroll
        for (int c = 0; c < CCLS; c++) {
            float v = __ldcs(base + c * HW);  // streaming: no reuse, don't pollute L2
            x[c] = v;
            m = fmaxf(m, v);
            xt = (c == tc) ? v : xt;
        }
        float s = 0.f;
        #pragma unroll
        for (int c = 0; c < CCLS; c++) s += __expf(x[c] - m);
        const float lp = xt - m - __logf(s);  // log_softmax at target class

        const int nc = n * CCLS + tc;
        atomicAdd(&sh_seg[nc], lp);
        atomicAdd(&sh_sc[nc], 1u);

        const float e = edgein[pix];
        if (e > 0.8f) {                       // edge-attention branch keeps label
            atomicAdd(&sh_att[nc], lp);
            atomicAdd(&sh_ac[nc], 1u);
        }

        // Stable BCE-with-logits; class-balance weights applied in finalize.
        const int em = edgemask[pix];         // 0 or 1
        const float te = (float)em;
        const float b = fmaxf(e, 0.f) - e * te + log1pf(__expf(-fabsf(e)));
        if (em) { bp += b; pc++; } else { bn += b; }
    }

    // Block-reduce BCE partials (warp shuffle -> shared -> one atomic per block)
    #pragma unroll
    for (int o = 16; o; o >>= 1) {
        bp += __shfl_down_sync(0xffffffffu, bp, o);
        bn += __shfl_down_sync(0xffffffffu, bn, o);
        pc += __shfl_down_sync(0xffffffffu, pc, o);
    }
    const int wid = t >> 5, lid = t & 31;
    if (lid == 0) { swp[wid] = bp; swn[wid] = bn; swc[wid] = pc; }
    __syncthreads();  // also fences all shared-bin atomics above

    if (t == 0) {
        float tbp = 0.f, tbn = 0.f; unsigned int tpc = 0u;
        #pragma unroll
        for (int w = 0; w < NTHR / 32; w++) { tbp += swp[w]; tbn += swn[w]; tpc += swc[w]; }
        atomicAdd(&g_bpos, (double)tbp);
        atomicAdd(&g_bneg, (double)tbn);
        atomicAdd(&g_posn, (unsigned long long)tpc);
    }

    // Flush per-block class bins to global double accumulators
    for (int i = t; i < NC; i += NTHR) {
        if (sh_sc[i]) { atomicAdd(&g_segsum[i], (double)sh_seg[i]); atomicAdd(&g_scnt[i], sh_sc[i]); }
        if (sh_ac[i]) { atomicAdd(&g_attsum[i], (double)sh_att[i]); atomicAdd(&g_acnt[i], sh_ac[i]); }
    }
}

__global__ void finalize_kernel(float* out, int out_size) {
    const int t = threadIdx.x;
    for (int i = t; i < out_size; i += blockDim.x) out[i] = 0.f;
    __syncthreads();
    if (t == 0) {
        double loss = 0.0;

        // seg loss (SEG_W = 1.0): weighted NLL mean per image, summed
        for (int n = 0; n < NIMG; n++) {
            double tot = 0.0;
            for (int c = 0; c < CCLS; c++) tot += (double)g_scnt[n * CCLS + c];
            double num = 0.0, den = 0.0;
            for (int c = 0; c < CCLS; c++) {
                const double cnt = (double)g_scnt[n * CCLS + c];
                if (cnt > 0.0) {
                    const double w = 2.0 - cnt / tot;  // (bins!=0)*1*(1-hist)+1
                    num -= w * g_segsum[n * CCLS + c];
                    den += w * cnt;
                }
            }
            loss += num / den;
        }

        // att loss (ATT_W = 0.1): same but on edge-attended pixels only
        for (int n = 0; n < NIMG; n++) {
            double tot = 0.0;
            for (int c = 0; c < CCLS; c++) tot += (double)g_acnt[n * CCLS + c];
            double num = 0.0, den = 0.0;
            for (int c = 0; c < CCLS; c++) {
                const double cnt = (double)g_acnt[n * CCLS + c];
                if (cnt > 0.0) {
                    const double w = 2.0 - cnt / tot;
                    num -= w * g_attsum[n * CCLS + c];
                    den += w * cnt;
                }
            }
            loss += 0.1 * (num / den);
        }

        // edge loss (EDGE_W = 0.3): class-balanced BCE mean
        const double posn = (double)g_posn;
        const double negn = (double)TOT - posn;
        const double edge = (negn * g_bpos + posn * g_bneg) / ((double)TOT * (double)TOT);
        loss += 0.3 * edge;

        out[0] = (float)loss;
    }
}

extern "C" void kernel_launch(void* const* d_in, const int* in_sizes, int n_in,
                              void* d_out, int out_size) {
    const float* segin    = (const float*)d_in[0];
    const float* edgein   = (const float*)d_in[1];
    const int*   segmask  = (const int*)d_in[2];
    const int*   edgemask = (const int*)d_in[3];
    float* out = (float*)d_out;

    zero_kernel<<<1, 128>>>();
    main_kernel<<<NBLK, NTHR>>>(segin, edgein, segmask, edgemask);
    finalize_kernel<<<1, 256>>>(out, out_size);
}

// round 3
// speedup vs baseline: 1.3154x; 1.3154x over previous
#include <cuda_runtime.h>

#define CCLS 19
#define NIMG 4
#define HDIM 768
#define HW (HDIM*HDIM)        /* 589824 */
#define TOT (NIMG*HW)         /* 2359296 */
#define GPI (HW/4)            /* 147456 float4-groups per image */
#define IB  144               /* blocks per image: GPI / (IB*256) = 4 exactly */
#define NTHR 256
#define NWARP (NTHR/32)

// ---- inter-kernel buffers (static device memory, no allocs) ----
__device__ unsigned int g_hseg[NIMG][IB][CCLS];
__device__ unsigned int g_hatt[NIMG][IB][CCLS];
__device__ float        g_bp[NIMG][IB];
__device__ float        g_bn[NIMG][IB];
__device__ unsigned int g_pc[NIMG][IB];

__device__ float  g_wseg[NIMG][CCLS];
__device__ float  g_watt[NIMG][CCLS];
__device__ double g_dseg[NIMG];
__device__ double g_datt[NIMG];
__device__ double g_edge;

__device__ double g_nseg[NIMG][IB];
__device__ double g_natt[NIMG][IB];

// ============================================================
// Kernel 1: histograms of segmask / attended segmask + BCE partials.
// Touches only segmask, edgein, edgemask (28 MB). No segin.
// ============================================================
__global__ __launch_bounds__(NTHR) void hist_kernel(
    const int* __restrict__ segmask, const float* __restrict__ edgein,
    const int* __restrict__ edgemask)
{
    const int n = blockIdx.y, b = blockIdx.x, t = threadIdx.x;
    const int wid = t >> 5, lid = t & 31;

    __shared__ unsigned int wseg[NWARP][CCLS];
    __shared__ unsigned int watt[NWARP][CCLS];
    __shared__ float  sbp[NWARP], sbn[NWARP];
    __shared__ unsigned int spc[NWARP];

    for (int i = t; i < NWARP * CCLS; i += NTHR) {
        ((unsigned int*)wseg)[i] = 0u; ((unsigned int*)watt)[i] = 0u;
    }
    __syncthreads();

    const int4*   sm4 = (const int4*)(segmask + (size_t)n * HW);
    const float4* e4p = (const float4*)(edgein  + (size_t)n * HW);
    const int4*   em4 = (const int4*)(edgemask + (size_t)n * HW);

    float bp = 0.f, bn = 0.f; unsigned int pc = 0;

    for (int gi = b * NTHR + t; gi < GPI; gi += IB * NTHR) {
        const int4   tc = sm4[gi];
        const float4 e  = e4p[gi];
        const int4   em = em4[gi];

        #define DO_PX(TCJ, EJ, EMJ) do {                                      \
            unsigned int m = __match_any_sync(0xffffffffu, (TCJ));            \
            if (lid == __ffs(m) - 1)                                          \
                atomicAdd(&wseg[wid][(TCJ)], __popc(m));                      \
            const bool att = (EJ) > 0.8f;                                     \
            unsigned int am = __ballot_sync(0xffffffffu, att);                \
            if (att) {                                                        \
                unsigned int m2 = __match_any_sync(am, (TCJ));                \
                if (lid == __ffs(m2) - 1)                                     \
                    atomicAdd(&watt[wid][(TCJ)], __popc(m2));                 \
            }                                                                 \
            const float bce = fmaxf((EJ), 0.f) - (EJ) * (float)(EMJ)         \
                            + __logf(1.f + __expf(-fabsf(EJ)));               \
            bp += (EMJ) ? bce : 0.f;                                          \
            bn += (EMJ) ? 0.f : bce;                                          \
            pc += (unsigned)(EMJ);                                            \
        } while (0)

        DO_PX(tc.x, e.x, em.x);
        DO_PX(tc.y, e.y, em.y);
        DO_PX(tc.z, e.z, em.z);
        DO_PX(tc.w, e.w, em.w);
        #undef DO_PX
    }

    // BCE warp reduce
    #pragma unroll
    for (int o = 16; o; o >>= 1) {
        bp += __shfl_down_sync(0xffffffffu, bp, o);
        bn += __shfl_down_sync(0xffffffffu, bn, o);
        pc += __shfl_down_sync(0xffffffffu, pc, o);
    }
    if (lid == 0) { sbp[wid] = bp; sbn[wid] = bn; spc[wid] = pc; }
    __syncthreads();

    if (t == 0) {
        float tp = 0.f, tn = 0.f; unsigned int tc2 = 0;
        #pragma unroll
        for (int w = 0; w < NWARP; w++) { tp += sbp[w]; tn += sbn[w]; tc2 += spc[w]; }
        g_bp[n][b] = tp; g_bn[n][b] = tn; g_pc[n][b] = tc2;
    }
    if (t < CCLS) {
        unsigned int s = 0, a = 0;
        #pragma unroll
        for (int w = 0; w < NWARP; w++) { s += wseg[w][t]; a += watt[w][t]; }
        g_hseg[n][b][t] = s; g_hatt[n][b][t] = a;
    }
}

// ============================================================
// Kernel 2: reduce histograms -> class weights, dens, edge loss.
// ============================================================
__global__ void weights_kernel() {
    const int t = threadIdx.x;
    __shared__ double cs[NIMG][CCLS], ca[NIMG][CCLS];
    __shared__ double rb[NWARP], rn2[NWARP], rp[NWARP];

    if (t < NIMG * CCLS) {
        const int n = t / CCLS, c = t - n * CCLS;
        double s = 0.0, a = 0.0;
        for (int b = 0; b < IB; b++) { s += (double)g_hseg[n][b][c]; a += (double)g_hatt[n][b][c]; }
        cs[n][c] = s; ca[n][c] = a;
    }
    __syncthreads();
    if (t < NIMG * CCLS) {
        const int n = t / CCLS, c = t - n * CCLS;
        double tot = 0.0, ta = 0.0;
        for (int c2 = 0; c2 < CCLS; c2++) { tot += cs[n][c2]; ta += ca[n][c2]; }
        g_wseg[n][c] = (float)(2.0 - cs[n][c] / tot);
        g_watt[n][c] = (ta > 0.0) ? (float)(2.0 - ca[n][c] / ta) : 1.0f;
    }
    __syncthreads();
    if (t < NIMG) {
        double ds = 0.0, da = 0.0;
        for (int c = 0; c < CCLS; c++) {
            ds += (double)g_wseg[t][c] * cs[t][c];
            da += (double)g_watt[t][c] * ca[t][c];
        }
        g_dseg[t] = ds; g_datt[t] = da;
    }

    // BCE global reduce
    double bp = 0.0, bn = 0.0, pc = 0.0;
    for (int i = t; i < NIMG * IB; i += blockDim.x) {
        const int n = i / IB, b = i - n * IB;
        bp += (double)g_bp[n][b]; bn += (double)g_bn[n][b]; pc += (double)g_pc[n][b];
    }
    #pragma unroll
    for (int o = 16; o; o >>= 1) {
        bp += __shfl_down_sync(0xffffffffu, bp, o);
        bn += __shfl_down_sync(0xffffffffu, bn, o);
        pc += __shfl_down_sync(0xffffffffu, pc, o);
    }
    const int wid = t >> 5, lid = t & 31;
    if (lid == 0) { rb[wid] = bp; rn2[wid] = bn; rp[wid] = pc; }
    __syncthreads();
    if (t == 0) {
        double tbp = 0.0, tbn = 0.0, tpc = 0.0;
        #pragma unroll
        for (int w = 0; w < NWARP; w++) { tbp += rb[w]; tbn += rn2[w]; tpc += rp[w]; }
        const double negn = (double)TOT - tpc;
        g_edge = (negn * tbp + tpc * tbn) / ((double)TOT * (double)TOT);
    }
}

// ============================================================
// Kernel 3: heavy pass over segin. Atomic-free; 4 pixels/thread (float4).
// ============================================================
__global__ __launch_bounds__(NTHR) void main_kernel(
    const float* __restrict__ segin, const float* __restrict__ edgein,
    const int* __restrict__ segmask)
{
    const int n = blockIdx.y, b = blockIdx.x, t = threadIdx.x;
    __shared__ float ws[CCLS], wa[CCLS];
    __shared__ double rs[NWARP], ra[NWARP];

    if (t < CCLS) { ws[t] = g_wseg[n][t]; wa[t] = g_watt[n][t]; }
    __syncthreads();

    const float4* seg4 = (const float4*)segin + (size_t)n * CCLS * GPI;
    const int4*   sm4  = (const int4*)(segmask + (size_t)n * HW);
    const float4* e4p  = (const float4*)(edgein + (size_t)n * HW);

    float as = 0.f, aa = 0.f;

    for (int gi = b * NTHR + t; gi < GPI; gi += IB * NTHR) {
        const int4   tc = sm4[gi];
        const float4 e  = e4p[gi];
        float s0 = 0.f, s1 = 0.f, s2 = 0.f, s3 = 0.f;
        float x0 = 0.f, x1 = 0.f, x2 = 0.f, x3 = 0.f;
        #pragma unroll
        for (int c = 0; c < CCLS; c++) {
            const float4 v = __ldcs(seg4 + (size_t)c * GPI + gi);
            s0 += __expf(v.x); x0 = (c == tc.x) ? v.x : x0;
            s1 += __expf(v.y); x1 = (c == tc.y) ? v.y : x1;
            s2 += __expf(v.z); x2 = (c == tc.z) ? v.z : x2;
            s3 += __expf(v.w); x3 = (c == tc.w) ? v.w : x3;
        }
        const float lp0 = x0 - __logf(s0);
        const float lp1 = x1 - __logf(s1);
        const float lp2 = x2 - __logf(s2);
        const float lp3 = x3 - __logf(s3);

        as += ws[tc.x] * lp0 + ws[tc.y] * lp1 + ws[tc.z] * lp2 + ws[tc.w] * lp3;
        aa += (e.x > 0.8f ? wa[tc.x] * lp0 : 0.f)
            + (e.y > 0.8f ? wa[tc.y] * lp1 : 0.f)
            + (e.z > 0.8f ? wa[tc.z] * lp2 : 0.f)
            + (e.w > 0.8f ? wa[tc.w] * lp3 : 0.f);
    }

    #pragma unroll
    for (int o = 16; o; o >>= 1) {
        as += __shfl_down_sync(0xffffffffu, as, o);
        aa += __shfl_down_sync(0xffffffffu, aa, o);
    }
    const int wid = t >> 5, lid = t & 31;
    if (lid == 0) { rs[wid] = (double)as; ra[wid] = (double)aa; }
    __syncthreads();
    if (t == 0) {
        double ts = 0.0, ta = 0.0;
        #pragma unroll
        for (int w = 0; w < NWARP; w++) { ts += rs[w]; ta += ra[w]; }
        g_nseg[n][b] = ts; g_natt[n][b] = ta;
    }
}

// ============================================================
// Kernel 4: final combine.
// ============================================================
__global__ void finalize_kernel(float* out, int out_size) {
    const int t = threadIdx.x;
    for (int i = t; i < out_size; i += blockDim.x) out[i] = 0.f;
    __shared__ double sv[8];
    if (t < 8) {
        const int n = t & 3, which = t >> 2;
        double s = 0.0;
        for (int b = 0; b < IB; b++) s += which ? g_natt[n][b] : g_nseg[n][b];
        sv[t] = s;
    }
    __syncthreads();
    if (t == 0) {
        double loss = 0.3 * g_edge;
        for (int n = 0; n < NIMG; n++) {
            loss += (-sv[n]) / g_dseg[n];                       // SEG_W = 1.0
            if (g_datt[n] > 0.0) loss += 0.1 * (-sv[4 + n]) / g_datt[n];  // ATT_W
        }
        out[0] = (float)loss;
    }
}

extern "C" void kernel_launch(void* const* d_in, const int* in_sizes, int n_in,
                              void* d_out, int out_size) {
    const float* segin    = (const float*)d_in[0];
    const float* edgein   = (const float*)d_in[1];
    const int*   segmask  = (const int*)d_in[2];
    const int*   edgemask = (const int*)d_in[3];
    float* out = (float*)d_out;

    dim3 grid(IB, NIMG);
    hist_kernel<<<grid, NTHR>>>(segmask, edgein, edgemask);
    weights_kernel<<<1, NTHR>>>();
    main_kernel<<<grid, NTHR>>>(segin, edgein, segmask);
    finalize_kernel<<<1, 64>>>(out, out_size);
}